// round 15
// baseline (speedup 1.0000x reference)
#include <cuda_runtime.h>
#include <cstdint>

#define EMBED 1024
#define DFF   4096
#define NBATCH 4
#define SEQ   2048
#define NROWS (NBATCH * SEQ)   // 8192

// ---------------- scratch (device globals: no allocations allowed) ----------
__device__ float    g_S   [(size_t)NBATCH * SEQ * SEQ];    // raw scores (f32)
__device__ float    g_T   [NROWS * EMBED];                 // ff2 out (f32)
__device__ float    g_AO  [NROWS * EMBED];                 // wo-gemm out (f32)
__device__ float    g_X   [NROWS * EMBED];                 // LN1 out f32 (residual)
__device__ float    g_Vp  [NROWS * EMBED];                 // V proj out (f32)
// fp16x2 packed operands
__device__ __align__(16) uint32_t g_SrcH[NROWS * EMBED/2];
__device__ __align__(16) uint32_t g_XH  [NROWS * EMBED/2];
__device__ __align__(16) uint32_t g_AoH [NROWS * EMBED/2];
__device__ __align__(16) uint32_t g_FH  [(size_t)NROWS * DFF/2];
__device__ __align__(16) uint32_t g_AtH [(size_t)NBATCH * SEQ * SEQ/2];
__device__ __align__(16) uint32_t g_VtH [(size_t)NBATCH * EMBED * SEQ/2];
__device__ __align__(16) uint32_t g_WvtH[EMBED * EMBED/2];
__device__ __align__(16) uint32_t g_WotH[EMBED * EMBED/2];
__device__ __align__(16) uint32_t g_W1tH[(size_t)DFF * EMBED/2];
__device__ __align__(16) uint32_t g_W2tH[(size_t)EMBED * DFF/2];
// bf16 hi/lo packed (scores path)
__device__ __align__(16) uint32_t g_Sh [NROWS * EMBED/2], g_Sl [NROWS * EMBED/2];
__device__ __align__(16) uint32_t g_Qh [NROWS * EMBED/2], g_Ql [NROWS * EMBED/2];
__device__ __align__(16) uint32_t g_Kh [NROWS * EMBED/2], g_Kl [NROWS * EMBED/2];
__device__ __align__(16) uint32_t g_Wqh[EMBED * EMBED/2], g_Wql[EMBED * EMBED/2];
__device__ __align__(16) uint32_t g_Wkh[EMBED * EMBED/2], g_Wkl[EMBED * EMBED/2];

// ---------------- helpers ----------------------------------------------------
__device__ __forceinline__ uint32_t bfpack(float e0, float e1) {
    uint32_t d; asm("cvt.rn.bf16x2.f32 %0, %1, %2;" : "=r"(d) : "f"(e1), "f"(e0)); return d;
}
__device__ __forceinline__ uint32_t bfres(float e0, float e1, uint32_t h) {
    float h0 = __uint_as_float(h << 16);
    float h1 = __uint_as_float(h & 0xffff0000u);
    return bfpack(e0 - h0, e1 - h1);
}
__device__ __forceinline__ uint32_t hpack(float e0, float e1) {   // lo=e0, hi=e1
    uint32_t d; asm("cvt.rn.f16x2.f32 %0, %1, %2;" : "=r"(d) : "f"(e1), "f"(e0)); return d;
}

#define CP16(dst, src) \
    asm volatile("cp.async.cg.shared.global [%0], [%1], 16;" :: "r"(dst), "l"(src))
#define CP_COMMIT()  asm volatile("cp.async.commit_group;" ::: "memory")
#define CP_WAIT1()   asm volatile("cp.async.wait_group 1;" ::: "memory")
#define CP_WAIT0()   asm volatile("cp.async.wait_group 0;" ::: "memory")

#define LDSM4(r0, r1, r2, r3, addr) \
    asm volatile("ldmatrix.sync.aligned.m8n8.x4.shared.b16 {%0,%1,%2,%3}, [%4];" \
        : "=r"(r0), "=r"(r1), "=r"(r2), "=r"(r3) : "r"(addr))

#define MMA_BF16(d, A0, A1, A2, A3, B0, B1) \
    asm volatile("mma.sync.aligned.m16n8k16.row.col.f32.bf16.bf16.f32 " \
        "{%0,%1,%2,%3},{%4,%5,%6,%7},{%8,%9},{%0,%1,%2,%3};" \
        : "+f"((d)[0]), "+f"((d)[1]), "+f"((d)[2]), "+f"((d)[3]) \
        : "r"(A0), "r"(A1), "r"(A2), "r"(A3), "r"(B0), "r"(B1))

#define MMA_F16(d, A0, A1, A2, A3, B0, B1) \
    asm volatile("mma.sync.aligned.m16n8k16.row.col.f32.f16.f16.f32 " \
        "{%0,%1,%2,%3},{%4,%5,%6,%7},{%8,%9},{%0,%1,%2,%3};" \
        : "+f"((d)[0]), "+f"((d)[1]), "+f"((d)[2]), "+f"((d)[3]) \
        : "r"(A0), "r"(A1), "r"(A2), "r"(A3), "r"(B0), "r"(B1))

// ============================================================================
// gemm_h: plain fp16 GEMM, LDSM loads, 3-stage cp.async pipeline.
// Block tile 256(M)x128(N), warp grid 4m x 2n, warp tile 64x64.
// A:[M][Kw] row pack; B:[N][Kw] k-major pack (C = A·B^T over k).
// K-tile 64 (32 words). SMEM stage 48KB: A 256x32w (32KB) | B 128x32w (16KB);
// word w of row r at r*32 + ((w>>2)^(r&7))*4 + (w&3). Per k16 step per warp:
// 4 A-LDSM + 4 B-LDSM -> 32 MMAs. One __syncthreads per k-tile.
// ============================================================================
template<int OUTPACK, int BIAS, int RELU>
__global__ void __launch_bounds__(256, 1)
gemm_h(const uint32_t* __restrict__ A, const uint32_t* __restrict__ B,
       const float* __restrict__ bias,
       float* __restrict__ C, uint32_t* __restrict__ Cp,
       int M, int N, int Kw,
       size_t sAw, size_t sBw, size_t sCo)
{
    A += (size_t)blockIdx.z * sAw;
    B += (size_t)blockIdx.z * sBw;
    if (OUTPACK) Cp += (size_t)blockIdx.z * sCo;
    else         C  += (size_t)blockIdx.z * sCo;

    extern __shared__ uint32_t smh[];   // 3 stages x 12288 words (48KB)
    const uint32_t smbase = (uint32_t)__cvta_generic_to_shared(smh);

    const int tid  = threadIdx.x;
    const int lane = tid & 31;
    const int wid  = tid >> 5;
    const int g    = lane >> 2;
    const int tig  = lane & 3;
    const int wm   = wid & 3;            // warp m (x64)
    const int wn   = wid >> 2;           // warp n (x64)
    const int row0 = blockIdx.y * 256;
    const int col0 = blockIdx.x * 128;
    const int nwB  = wn * 64;

    const int aHi  = lane >> 4;
    const int la15 = lane & 15;
    const int bHi  = (lane >> 3) & 1;
    const int rbl  = (lane & 7) + ((lane >> 4) << 3);

    float acc[4][8][4];
#pragma unroll
    for (int mi = 0; mi < 4; mi++)
#pragma unroll
        for (int ni = 0; ni < 8; ni++)
#pragma unroll
            for (int j = 0; j < 4; j++) acc[mi][ni][j] = 0.f;

    auto issue = [&](int ktw, int s) {
        const uint32_t sa = smbase + s * (12288 * 4);
        const uint32_t sb = sa + 8192 * 4;
#pragma unroll
        for (int i = 0; i < 8; i++) {                 // A: 256 rows x 8 chunks
            int flat = i * 256 + tid;
            int r = flat >> 3, c = flat & 7;
            const uint32_t* src = A + (size_t)(row0 + r) * Kw + ktw + c * 4;
            uint32_t dst = sa + (r * 32 + ((c ^ (r & 7)) << 2)) * 4;
            CP16(dst, src);
        }
#pragma unroll
        for (int i = 0; i < 4; i++) {                 // B: 128 rows x 8 chunks
            int flat = i * 256 + tid;
            int r = flat >> 3, c = flat & 7;
            const uint32_t* src = B + (size_t)(col0 + r) * Kw + ktw + c * 4;
            uint32_t dst = sb + (r * 32 + ((c ^ (r & 7)) << 2)) * 4;
            CP16(dst, src);
        }
        CP_COMMIT();
    };

    auto compute = [&](int s) {
        const uint32_t sA = smbase + s * (12288 * 4);
        const uint32_t sB = sA + 8192 * 4;
#pragma unroll
        for (int ks = 0; ks < 4; ks++) {
            uint32_t a[4][4];
#pragma unroll
            for (int mi = 0; mi < 4; mi++) {
                const int ra = wm * 64 + mi * 16 + la15;
                LDSM4(a[mi][0], a[mi][1], a[mi][2], a[mi][3],
                      sA + ra * 128 + (((2 * ks + aHi) ^ (ra & 7)) << 4));
            }
#pragma unroll
            for (int p = 0; p < 4; p++) {
                const int rb = nwB + p * 16 + rbl;
                uint32_t b0, b1, b2, b3;
                LDSM4(b0, b1, b2, b3,
                      sB + rb * 128 + (((2 * ks + bHi) ^ (rb & 7)) << 4));
#pragma unroll
                for (int mi = 0; mi < 4; mi++) {
                    MMA_F16(acc[mi][2*p],   a[mi][0], a[mi][1], a[mi][2], a[mi][3], b0, b1);
                    MMA_F16(acc[mi][2*p+1], a[mi][0], a[mi][1], a[mi][2], a[mi][3], b2, b3);
                }
            }
        }
    };

    const int ktiles = Kw / 32;
    issue(0, 0);
    if (ktiles > 1) issue(32, 1);
    for (int t = 0; t < ktiles; t++) {
        if (t + 1 < ktiles) CP_WAIT1(); else CP_WAIT0();
        __syncthreads();
        compute(t % 3);
        if (t + 2 < ktiles) issue((t + 2) * 32, (t + 2) % 3);
    }

#pragma unroll
    for (int mi = 0; mi < 4; mi++) {
        const int r0 = row0 + wm * 64 + mi * 16 + g;
#pragma unroll
        for (int ni = 0; ni < 8; ni++) {
            const int c = col0 + nwB + ni * 8 + tig * 2;
            float f0 = acc[mi][ni][0], f1 = acc[mi][ni][1];
            float f2 = acc[mi][ni][2], f3 = acc[mi][ni][3];
            if (BIAS) {
                const float2 bb = *(const float2*)&bias[c];
                f0 += bb.x; f1 += bb.y; f2 += bb.x; f3 += bb.y;
            }
            if (RELU) {
                f0 = fmaxf(f0, 0.f); f1 = fmaxf(f1, 0.f);
                f2 = fmaxf(f2, 0.f); f3 = fmaxf(f3, 0.f);
            }
            if (OUTPACK) {
                const int Nw = N >> 1, wc = c >> 1;
                Cp[(size_t)r0 * Nw + wc]       = hpack(f0, f1);
                Cp[(size_t)(r0 + 8) * Nw + wc] = hpack(f2, f3);
            } else {
                *(float2*)&C[(size_t)r0 * N + c]       = make_float2(f0, f1);
                *(float2*)&C[(size_t)(r0 + 8) * N + c] = make_float2(f2, f3);
            }
        }
    }
}

// ============================================================================
// gemm_p: bf16 hi/lo 3-term GEMM (scores path), LDSM loads, 3-stage pipeline.
// (unchanged from R13 — proven)
// ============================================================================
template<int OUTPACK, int BIAS>
__global__ void __launch_bounds__(256, 1)
gemm_p(const uint32_t* __restrict__ Ah, const uint32_t* __restrict__ Al,
       const uint32_t* __restrict__ Bh, const uint32_t* __restrict__ Bl,
       const float* __restrict__ bias,
       float* __restrict__ C, uint32_t* __restrict__ Ch, uint32_t* __restrict__ Cl,
       int M, int N, int Kw,
       size_t sAw, size_t sBw, size_t sCe)
{
    Ah += (size_t)blockIdx.z * sAw;  Al += (size_t)blockIdx.z * sAw;
    Bh += (size_t)blockIdx.z * sBw;  Bl += (size_t)blockIdx.z * sBw;
    if (!OUTPACK) C += (size_t)blockIdx.z * sCe;

    extern __shared__ uint32_t smp[];
    const uint32_t smbase = (uint32_t)__cvta_generic_to_shared(smp);

    const int tid  = threadIdx.x;
    const int lane = tid & 31;
    const int wid  = tid >> 5;
    const int g    = lane >> 2;
    const int tig  = lane & 3;
    const int wm   = wid & 1;
    const int wn   = wid >> 1;
    const int row0 = blockIdx.y * 128;
    const int col0 = blockIdx.x * 128;
    const int nwB  = wn * 32;

    const int aHi  = lane >> 4;
    const int la15 = lane & 15;
    const int bHi  = (lane >> 3) & 1;
    const int rbl  = (lane & 7) + ((lane >> 4) << 3);

    float acc[4][4][4];
#pragma unroll
    for (int mi = 0; mi < 4; mi++)
#pragma unroll
        for (int ni = 0; ni < 4; ni++)
#pragma unroll
            for (int j = 0; j < 4; j++) acc[mi][ni][j] = 0.f;

    auto issue = [&](int ktw, int s) {
        const uint32_t base = smbase + s * (8192 * 4);
        const uint32_t* gp[4] = { Ah, Al, Bh, Bl };
#pragma unroll
        for (int i = 0; i < 8; i++) {
            int flat = i * 256 + tid;
            int a    = flat >> 9;
            int rem  = flat & 511;
            int r    = rem >> 2;
            int c    = rem & 3;
            const int ro = (a < 2) ? row0 : col0;
            const uint32_t* src = gp[a] + (size_t)(ro + r) * Kw + ktw + c * 4;
            const int L = (a & 1) ? (c ^ 4) : c;
            const uint32_t side = (a < 2) ? 0u : 4096u * 4u;
            uint32_t dst = base + side + (r * 32 + ((L ^ (r & 7)) << 2)) * 4;
            CP16(dst, src);
        }
        CP_COMMIT();
    };

    auto compute = [&](int s) {
        const uint32_t sA = smbase + s * (8192 * 4);
        const uint32_t sB = sA + 4096 * 4;
#pragma unroll
        for (int ks = 0; ks < 2; ks++) {
            uint32_t ah[4][4], al[4][4];
#pragma unroll
            for (int mi = 0; mi < 4; mi++) {
                const int ra = wm * 64 + mi * 16 + la15;
                const uint32_t rbase = sA + ra * 128;
                const int ch = 2 * ks + aHi;
                LDSM4(ah[mi][0], ah[mi][1], ah[mi][2], ah[mi][3],
                      rbase + ((ch ^ (ra & 7)) << 4));
                LDSM4(al[mi][0], al[mi][1], al[mi][2], al[mi][3],
                      rbase + (((ch ^ 4) ^ (ra & 7)) << 4));
            }
#pragma unroll
            for (int p = 0; p < 2; p++) {
                const int rb = nwB + p * 16 + rbl;
                const uint32_t rbase = sB + rb * 128;
                const int ch = 2 * ks + bHi;
                uint32_t bh0, bh1, bh2, bh3, bl0, bl1, bl2, bl3;
                LDSM4(bh0, bh1, bh2, bh3, rbase + ((ch ^ (rb & 7)) << 4));
                LDSM4(bl0, bl1, bl2, bl3, rbase + (((ch ^ 4) ^ (rb & 7)) << 4));
#pragma unroll
                for (int mi = 0; mi < 4; mi++) {
                    MMA_BF16(acc[mi][2*p],   ah[mi][0], ah[mi][1], ah[mi][2], ah[mi][3], bh0, bh1);
                    MMA_BF16(acc[mi][2*p+1], ah[mi][0], ah[mi][1], ah[mi][2], ah[mi][3], bh2, bh3);
                }
#pragma unroll
                for (int mi = 0; mi < 4; mi++) {
                    MMA_BF16(acc[mi][2*p],   al[mi][0], al[mi][1], al[mi][2], al[mi][3], bh0, bh1);
                    MMA_BF16(acc[mi][2*p+1], al[mi][0], al[mi][1], al[mi][2], al[mi][3], bh2, bh3);
                }
#pragma unroll
                for (int mi = 0; mi < 4; mi++) {
                    MMA_BF16(acc[mi][2*p],   ah[mi][0], ah[mi][1], ah[mi][2], ah[mi][3], bl0, bl1);
                    MMA_BF16(acc[mi][2*p+1], ah[mi][0], ah[mi][1], ah[mi][2], ah[mi][3], bl2, bl3);
                }
            }
        }
    };

    const int ktiles = Kw / 16;
    issue(0, 0);
    if (ktiles > 1) issue(16, 1);
    for (int t = 0; t < ktiles; t++) {
        if (t + 1 < ktiles) CP_WAIT1(); else CP_WAIT0();
        __syncthreads();
        compute(t % 3);
        if (t + 2 < ktiles) issue((t + 2) * 16, (t + 2) % 3);
    }

#pragma unroll
    for (int mi = 0; mi < 4; mi++) {
        const int r0 = row0 + wm * 64 + mi * 16 + g;
#pragma unroll
        for (int ni = 0; ni < 4; ni++) {
            const int c = col0 + nwB + ni * 8 + tig * 2;
            float f0 = acc[mi][ni][0], f1 = acc[mi][ni][1];
            float f2 = acc[mi][ni][2], f3 = acc[mi][ni][3];
            if (BIAS) {
                const float2 bb = *(const float2*)&bias[c];
                f0 += bb.x; f1 += bb.y; f2 += bb.x; f3 += bb.y;
            }
            if (OUTPACK) {
                const int Nw = N >> 1, wc = c >> 1;
                uint32_t h0 = bfpack(f0, f1), h1 = bfpack(f2, f3);
                Ch[(size_t)r0 * Nw + wc]       = h0;
                Cl[(size_t)r0 * Nw + wc]       = bfres(f0, f1, h0);
                Ch[(size_t)(r0 + 8) * Nw + wc] = h1;
                Cl[(size_t)(r0 + 8) * Nw + wc] = bfres(f2, f3, h1);
            } else {
                *(float2*)&C[(size_t)r0 * N + c]       = make_float2(f0, f1);
                *(float2*)&C[(size_t)(r0 + 8) * N + c] = make_float2(f2, f3);
            }
        }
    }
}

// ---------------- pre-pass kernels ------------------------------------------
__global__ void pack_src2(const float* __restrict__ src,
                          uint32_t* __restrict__ Sh, uint32_t* __restrict__ Sl,
                          uint32_t* __restrict__ SrcH)
{
    const size_t row = blockIdx.x;
    const int t = threadIdx.x;
#pragma unroll
    for (int j = 0; j < 2; j++) {
        const int p = t + j * 256;
        const float2 v = *(const float2*)(src + row * EMBED + 2 * p);
        uint32_t h = bfpack(v.x, v.y);
        Sh[row * (EMBED/2) + p] = h;
        Sl[row * (EMBED/2) + p] = bfres(v.x, v.y, h);
        SrcH[row * (EMBED/2) + p] = hpack(v.x, v.y);
    }
}

__global__ void tpack_h(const float* __restrict__ A, uint32_t* __restrict__ At,
                        int K, int N, size_t sA, size_t sAt)
{
    A  += (size_t)blockIdx.z * sA;
    At += (size_t)blockIdx.z * sAt;
    __shared__ float tile[64][65];
    const int k0 = blockIdx.y * 64, n0 = blockIdx.x * 64;
    const int t = threadIdx.x;
#pragma unroll
    for (int i = 0; i < 4; i++) {
        int flat = i * 256 + t;
        int r = flat >> 4, c = (flat & 15) * 4;
        float4 v = *(const float4*)(A + (size_t)(k0 + r) * N + n0 + c);
        tile[r][c]     = v.x;
        tile[r][c + 1] = v.y;
        tile[r][c + 2] = v.z;
        tile[r][c + 3] = v.w;
    }
    __syncthreads();
#pragma unroll
    for (int i = 0; i < 8; i++) {
        int flat = i * 256 + t;
        int n = flat >> 5, w = flat & 31;
        At[(size_t)(n0 + n) * (K >> 1) + (k0 >> 1) + w] =
            hpack(tile[2 * w][n], tile[2 * w + 1][n]);
    }
}

__global__ void tpack_bf(const float* __restrict__ W,
                         uint32_t* __restrict__ Wh, uint32_t* __restrict__ Wl,
                         int K, int N)
{
    __shared__ float tile[64][65];
    const int k0 = blockIdx.y * 64, n0 = blockIdx.x * 64;
    const int t = threadIdx.x;
#pragma unroll
    for (int i = 0; i < 4; i++) {
        int flat = i * 256 + t;
        int r = flat >> 4, c = (flat & 15) * 4;
        float4 v = *(const float4*)(W + (size_t)(k0 + r) * N + n0 + c);
        tile[r][c]     = v.x;
        tile[r][c + 1] = v.y;
        tile[r][c + 2] = v.z;
        tile[r][c + 3] = v.w;
    }
    __syncthreads();
#pragma unroll
    for (int i = 0; i < 8; i++) {
        int flat = i * 256 + t;
        int n = flat >> 5, w = flat & 31;
        float e0 = tile[2 * w][n], e1 = tile[2 * w + 1][n];
        uint32_t h = bfpack(e0, e1);
        Wh[(size_t)(n0 + n) * (K >> 1) + (k0 >> 1) + w] = h;
        Wl[(size_t)(n0 + n) * (K >> 1) + (k0 >> 1) + w] = bfres(e0, e1, h);
    }
}

// ---------------- softmax: read raw scores, emit packed fp16 attn ------------
__global__ void softmax_kernel(const float* __restrict__ S, uint32_t* __restrict__ AtH)
{
    const float* p = S + (size_t)blockIdx.x * SEQ;
    uint32_t* q = AtH + (size_t)blockIdx.x * (SEQ/2);
    const int tid  = threadIdx.x;
    const int lane = tid & 31;
    const int warp = tid >> 5;

    float4 v0 = ((const float4*)p)[tid];
    float4 v1 = ((const float4*)p)[tid + 256];

    __shared__ float sh[8];

    float m = fmaxf(fmaxf(fmaxf(v0.x, v0.y), fmaxf(v0.z, v0.w)),
                    fmaxf(fmaxf(v1.x, v1.y), fmaxf(v1.z, v1.w)));
#pragma unroll
    for (int o = 16; o > 0; o >>= 1) m = fmaxf(m, __shfl_xor_sync(0xffffffffu, m, o));
    if (lane == 0) sh[warp] = m;
    __syncthreads();
    if (tid < 32) {
        float t = (tid < 8) ? sh[tid] : -3.402823e38f;
#pragma unroll
        for (int o = 4; o > 0; o >>= 1) t = fmaxf(t, __shfl_xor_sync(0xffffffffu, t, o));
        if (tid == 0) sh[0] = t;
    }
    __syncthreads();
    m = sh[0];
    __syncthreads();

    v0.x = __expf(v0.x - m); v0.y = __expf(v0.y - m);
    v0.z = __expf(v0.z - m); v0.w = __expf(v0.w - m);
    v1.x = __expf(v1.x - m); v1.y = __expf(v1.y - m);
    v1.z = __expf(v1.z - m); v1.w = __expf(v1.w - m);

    float s = v0.x + v0.y + v0.z + v0.w + v1.x + v1.y + v1.z + v1.w;
#pragma unroll
    for (int o = 16; o > 0; o >>= 1) s += __shfl_xor_sync(0xffffffffu, s, o);
    if (lane == 0) sh[warp] = s;
    __syncthreads();
    if (tid < 32) {
        float t = (tid < 8) ? sh[tid] : 0.f;
#pragma unroll
        for (int o = 4; o > 0; o >>= 1) t += __shfl_xor_sync(0xffffffffu, t, o);
        if (tid == 0) sh[0] = t;
    }
    __syncthreads();
    const float r = 1.f / sh[0];

    q[2*tid]           = hpack(v0.x * r, v0.y * r);
    q[2*tid + 1]       = hpack(v0.z * r, v0.w * r);
    q[512 + 2*tid]     = hpack(v1.x * r, v1.y * r);
    q[512 + 2*tid + 1] = hpack(v1.z * r, v1.w * r);
}

// ---------------- residual + layernorm --------------------------------------
template<int WR>
__global__ void add_ln_kernel(const float* __restrict__ X, const float* __restrict__ Y,
                              const float* __restrict__ g, const float* __restrict__ b,
                              float* __restrict__ O, uint32_t* __restrict__ OH)
{
    const size_t row = blockIdx.x;
    const int tid  = threadIdx.x;
    const int lane = tid & 31;
    const int warp = tid >> 5;

    const float4 x = ((const float4*)(X + row * EMBED))[tid];
    const float4 y = ((const float4*)(Y + row * EMBED))[tid];
    float4 v;
    v.x = x.x + y.x; v.y = x.y + y.y; v.z = x.z + y.z; v.w = x.w + y.w;

    float s1 = v.x + v.y + v.z + v.w;
    float s2 = v.x * v.x + v.y * v.y + v.z * v.z + v.w * v.w;

    __shared__ float sh1[8], sh2[8];
#pragma unroll
    for (int o = 16; o > 0; o >>= 1) {
        s1 += __shfl_xor_sync(0xffffffffu, s1, o);
        s2 += __shfl_xor_sync(0xffffffffu, s2, o);
    }
    if (lane == 0) { sh1[warp] = s1; sh2[warp] = s2; }
    __syncthreads();
    if (tid < 32) {
        float t1 = (tid < 8) ? sh1[tid] : 0.f;
        float t2 = (tid < 8) ? sh2[tid] : 0.f;
#pragma unroll
        for (int o = 4; o > 0; o >>= 1) {
            t1 += __shfl_xor_sync(0xffffffffu, t1, o);
            t2 += __shfl_xor_sync(0xffffffffu, t2, o);
        }
        if (tid == 0) { sh1[0] = t1; sh2[0] = t2; }
    }
    __syncthreads();

    const float inv = 1.f / (float)EMBED;
    const float mu  = sh1[0] * inv;
    const float var = sh2[0] * inv - mu * mu;
    const float r   = rsqrtf(var + 1e-5f);

    const float4 gg = ((const float4*)g)[tid];
    const float4 bb = ((const float4*)b)[tid];
    float4 o;
    o.x = (v.x - mu) * r * gg.x + bb.x;
    o.y = (v.y - mu) * r * gg.y + bb.y;
    o.z = (v.z - mu) * r * gg.z + bb.z;
    o.w = (v.w - mu) * r * gg.w + bb.w;
    ((float4*)(O + row * EMBED))[tid] = o;
    if (WR) {
        OH[row * (EMBED/2) + 2*tid]     = hpack(o.x, o.y);
        OH[row * (EMBED/2) + 2*tid + 1] = hpack(o.z, o.w);
    }
}

// ---------------- launch -----------------------------------------------------
extern "C" void kernel_launch(void* const* d_in, const int* in_sizes, int n_in,
                              void* d_out, int out_size)
{
    const float* src = (const float*)d_in[0];
    const float* Wq  = (const float*)d_in[1];
    const float* bq  = (const float*)d_in[2];
    const float* Wk  = (const float*)d_in[3];
    const float* bk  = (const float*)d_in[4];
    const float* Wv  = (const float*)d_in[5];
    const float* bv  = (const float*)d_in[6];
    const float* Wo  = (const float*)d_in[7];
    const float* bo  = (const float*)d_in[8];
    const float* W1  = (const float*)d_in[9];
    const float* b1  = (const float*)d_in[10];
    const float* W2  = (const float*)d_in[11];
    const float* b2  = (const float*)d_in[12];
    const float* g1  = (const float*)d_in[13];
    const float* be1 = (const float*)d_in[14];
    const float* g2  = (const float*)d_in[15];
    const float* be2 = (const float*)d_in[16];

    float *S, *T, *AO, *X, *Vp;
    uint32_t *SrcH, *XH, *AoH, *FH, *AtH, *VtH, *WvtH, *WotH, *W1tH, *W2tH;
    uint32_t *Sh, *Sl, *Qh, *Ql, *Kh, *Kl, *Wqh, *Wql, *Wkh, *Wkl;
    cudaGetSymbolAddress((void**)&S,    g_S);
    cudaGetSymbolAddress((void**)&T,    g_T);
    cudaGetSymbolAddress((void**)&AO,   g_AO);
    cudaGetSymbolAddress((void**)&X,    g_X);
    cudaGetSymbolAddress((void**)&Vp,   g_Vp);
    cudaGetSymbolAddress((void**)&SrcH, g_SrcH);
    cudaGetSymbolAddress((void**)&XH,   g_XH);
    cudaGetSymbolAddress((void**)&AoH,  g_AoH);
    cudaGetSymbolAddress((void**)&FH,   g_FH);
    cudaGetSymbolAddress((void**)&AtH,  g_AtH);
    cudaGetSymbolAddress((void**)&VtH,  g_VtH);
    cudaGetSymbolAddress((void**)&WvtH, g_WvtH);
    cudaGetSymbolAddress((void**)&WotH, g_WotH);
    cudaGetSymbolAddress((void**)&W1tH, g_W1tH);
    cudaGetSymbolAddress((void**)&W2tH, g_W2tH);
    cudaGetSymbolAddress((void**)&Sh,   g_Sh);
    cudaGetSymbolAddress((void**)&Sl,   g_Sl);
    cudaGetSymbolAddress((void**)&Qh,   g_Qh);
    cudaGetSymbolAddress((void**)&Ql,   g_Ql);
    cudaGetSymbolAddress((void**)&Kh,   g_Kh);
    cudaGetSymbolAddress((void**)&Kl,   g_Kl);
    cudaGetSymbolAddress((void**)&Wqh,  g_Wqh);
    cudaGetSymbolAddress((void**)&Wql,  g_Wql);
    cudaGetSymbolAddress((void**)&Wkh,  g_Wkh);
    cudaGetSymbolAddress((void**)&Wkl,  g_Wkl);

    const int SMEM_P = 98304;    // gemm_p: 3 stages x 32KB
    const int SMEM_H = 147456;   // gemm_h: 3 stages x 48KB
    cudaFuncSetAttribute(gemm_p<1,1>,   cudaFuncAttributeMaxDynamicSharedMemorySize, SMEM_P);
    cudaFuncSetAttribute(gemm_p<0,0>,   cudaFuncAttributeMaxDynamicSharedMemorySize, SMEM_P);
    cudaFuncSetAttribute(gemm_h<0,1,0>, cudaFuncAttributeMaxDynamicSharedMemorySize, SMEM_H);
    cudaFuncSetAttribute(gemm_h<1,0,0>, cudaFuncAttributeMaxDynamicSharedMemorySize, SMEM_H);
    cudaFuncSetAttribute(gemm_h<1,1,1>, cudaFuncAttributeMaxDynamicSharedMemorySize, SMEM_H);

    const int KW = EMBED / 2;                       // 512 words
    const size_t sQEw = (size_t)SEQ * KW;
    const size_t sSS  = (size_t)SEQ * SEQ;
    const size_t sSSw = sSS / 2;
    const size_t sVt  = (size_t)EMBED * (SEQ/2);

    // launch order arranged so launch #4 (ncu capture slot) = gemm_h V-proj
    pack_src2<<<NROWS, 256>>>(src, Sh, Sl, SrcH);                       // 1
    tpack_h <<<dim3(16,16), 256>>>(Wv, WvtH, EMBED, EMBED, 0, 0);       // 2
    tpack_bf<<<dim3(16,16), 256>>>(Wq, Wqh, Wql, EMBED, EMBED);         // 3
    gemm_h<0,1,0><<<dim3(EMBED/128, NROWS/256), 256, SMEM_H>>>(SrcH, WvtH, bv,
        Vp, nullptr, NROWS, EMBED, KW, 0, 0, 0);                        // 4 <- profiled
    tpack_bf<<<dim3(16,16), 256>>>(Wk, Wkh, Wkl, EMBED, EMBED);
    tpack_h <<<dim3(16,16), 256>>>(Wo, WotH, EMBED, EMBED, 0, 0);
    tpack_h <<<dim3(64,16), 256>>>(W1, W1tH, EMBED, DFF,   0, 0);
    tpack_h <<<dim3(16,64), 256>>>(W2, W2tH, DFF,   EMBED, 0, 0);

    // Q, K projections (bf16 3-term, packed out)
    gemm_p<1,1><<<dim3(EMBED/128, NROWS/128), 256, SMEM_P>>>(Sh, Sl, Wqh, Wql, bq,
        nullptr, Qh, Ql, NROWS, EMBED, KW, 0, 0, 0);
    gemm_p<1,1><<<dim3(EMBED/128, NROWS/128), 256, SMEM_P>>>(Sh, Sl, Wkh, Wkl, bk,
        nullptr, Kh, Kl, NROWS, EMBED, KW, 0, 0, 0);

    // V^T pack per batch
    tpack_h<<<dim3(16, 32, NBATCH), 256>>>(Vp, VtH, SEQ, EMBED,
        (size_t)SEQ * EMBED, sVt);

    // scores = Q @ K^T (bf16 3-term) -> f32
    gemm_p<0,0><<<dim3(SEQ/128, SEQ/128, NBATCH), 256, SMEM_P>>>(Qh, Ql, Kh, Kl, nullptr,
        S, nullptr, nullptr, SEQ, SEQ, KW, sQEw, sQEw, sSS);

    // softmax -> packed fp16 attn
    softmax_kernel<<<NROWS, 256>>>(S, AtH);

    // ao = attn @ V (fp16) -> packed
    gemm_h<1,0,0><<<dim3(EMBED/128, SEQ/256, NBATCH), 256, SMEM_H>>>(AtH, VtH, nullptr,
        nullptr, AoH, SEQ, EMBED, SEQ/2, sSSw, sVt, sQEw);

    // out-proj (fp16) -> f32
    gemm_h<0,1,0><<<dim3(EMBED/128, NROWS/256), 256, SMEM_H>>>(AoH, WotH, bo,
        AO, nullptr, NROWS, EMBED, KW, 0, 0, 0);

    add_ln_kernel<1><<<NROWS, 256>>>(src, AO, g1, be1, X, XH);

    // ff1 = relu(x @ W1 + b1) (fp16) -> packed
    gemm_h<1,1,1><<<dim3(DFF/128, NROWS/256), 256, SMEM_H>>>(XH, W1tH, b1,
        nullptr, FH, NROWS, DFF, KW, 0, 0, 0);

    // ff2 (fp16) -> f32
    gemm_h<0,1,0><<<dim3(EMBED/128, NROWS/256), 256, SMEM_H>>>(FH, W2tH, b2,
        T, nullptr, NROWS, EMBED, DFF/2, 0, 0, 0);

    add_ln_kernel<0><<<NROWS, 256>>>(X, T, g2, be2, (float*)d_out, nullptr);
}

// round 16
// speedup vs baseline: 1.0939x; 1.0939x over previous
#include <cuda_runtime.h>
#include <cstdint>

#define EMBED 1024
#define DFF   4096
#define NBATCH 4
#define SEQ   2048
#define NROWS (NBATCH * SEQ)   // 8192

// ---------------- scratch (device globals: no allocations allowed) ----------
__device__ float    g_S   [(size_t)NBATCH * SEQ * SEQ];    // raw scores (f32)
__device__ float    g_T   [NROWS * EMBED];                 // ff2 out (f32)
__device__ float    g_AO  [NROWS * EMBED];                 // wo-gemm out (f32)
__device__ float    g_X   [NROWS * EMBED];                 // LN1 out f32 (residual)
__device__ float    g_Vp  [NROWS * EMBED];                 // V proj out (f32)
__device__ float    g_va  [EMBED];                         // Wq·bk
__device__ float    g_vb  [EMBED];                         // Wk·bq
__device__ float    g_u   [NROWS];                         // src·a + bq·bk
__device__ float    g_v   [NROWS];                         // src·b
// fp16x2 packed operands
__device__ __align__(16) uint32_t g_SrcH[NROWS * EMBED/2];
__device__ __align__(16) uint32_t g_XH  [NROWS * EMBED/2];
__device__ __align__(16) uint32_t g_AoH [NROWS * EMBED/2];
__device__ __align__(16) uint32_t g_FH  [(size_t)NROWS * DFF/2];
__device__ __align__(16) uint32_t g_AtH [(size_t)NBATCH * SEQ * SEQ/2];
__device__ __align__(16) uint32_t g_VtH [(size_t)NBATCH * EMBED * SEQ/2];
__device__ __align__(16) uint32_t g_WvtH[EMBED * EMBED/2];
__device__ __align__(16) uint32_t g_WotH[EMBED * EMBED/2];
__device__ __align__(16) uint32_t g_W1tH[(size_t)DFF * EMBED/2];
__device__ __align__(16) uint32_t g_W2tH[(size_t)EMBED * DFF/2];
// bf16 hi/lo packed (scores path)
__device__ __align__(16) uint32_t g_Sh [NROWS * EMBED/2], g_Sl [NROWS * EMBED/2];  // src rows
__device__ __align__(16) uint32_t g_Ph [NROWS * EMBED/2], g_Pl [NROWS * EMBED/2];  // P rows
__device__ __align__(16) uint32_t g_Mh [EMBED * EMBED/2], g_Ml [EMBED * EMBED/2];  // Mt rows
__device__ __align__(16) uint32_t g_Wqr[EMBED * EMBED/2], g_Wqrl[EMBED * EMBED/2]; // Wq rows
__device__ __align__(16) uint32_t g_Wkr[EMBED * EMBED/2], g_Wkrl[EMBED * EMBED/2]; // Wk rows

// ---------------- helpers ----------------------------------------------------
__device__ __forceinline__ uint32_t bfpack(float e0, float e1) {
    uint32_t d; asm("cvt.rn.bf16x2.f32 %0, %1, %2;" : "=r"(d) : "f"(e1), "f"(e0)); return d;
}
__device__ __forceinline__ uint32_t bfres(float e0, float e1, uint32_t h) {
    float h0 = __uint_as_float(h << 16);
    float h1 = __uint_as_float(h & 0xffff0000u);
    return bfpack(e0 - h0, e1 - h1);
}
__device__ __forceinline__ uint32_t hpack(float e0, float e1) {   // lo=e0, hi=e1
    uint32_t d; asm("cvt.rn.f16x2.f32 %0, %1, %2;" : "=r"(d) : "f"(e1), "f"(e0)); return d;
}

#define CP16(dst, src) \
    asm volatile("cp.async.cg.shared.global [%0], [%1], 16;" :: "r"(dst), "l"(src))
#define CP_COMMIT()  asm volatile("cp.async.commit_group;" ::: "memory")
#define CP_WAIT1()   asm volatile("cp.async.wait_group 1;" ::: "memory")
#define CP_WAIT0()   asm volatile("cp.async.wait_group 0;" ::: "memory")

#define LDSM4(r0, r1, r2, r3, addr) \
    asm volatile("ldmatrix.sync.aligned.m8n8.x4.shared.b16 {%0,%1,%2,%3}, [%4];" \
        : "=r"(r0), "=r"(r1), "=r"(r2), "=r"(r3) : "r"(addr))

#define MMA_BF16(d, A0, A1, A2, A3, B0, B1) \
    asm volatile("mma.sync.aligned.m16n8k16.row.col.f32.bf16.bf16.f32 " \
        "{%0,%1,%2,%3},{%4,%5,%6,%7},{%8,%9},{%0,%1,%2,%3};" \
        : "+f"((d)[0]), "+f"((d)[1]), "+f"((d)[2]), "+f"((d)[3]) \
        : "r"(A0), "r"(A1), "r"(A2), "r"(A3), "r"(B0), "r"(B1))

#define MMA_F16(d, A0, A1, A2, A3, B0, B1) \
    asm volatile("mma.sync.aligned.m16n8k16.row.col.f32.f16.f16.f32 " \
        "{%0,%1,%2,%3},{%4,%5,%6,%7},{%8,%9},{%0,%1,%2,%3};" \
        : "+f"((d)[0]), "+f"((d)[1]), "+f"((d)[2]), "+f"((d)[3]) \
        : "r"(A0), "r"(A1), "r"(A2), "r"(A3), "r"(B0), "r"(B1))

// ============================================================================
// gemm_h: plain fp16 GEMM, LDSM loads, 3-stage cp.async pipeline (R13 proven).
// Block tile 128x128x64k; A:[M][Kw] row pack; B:[N][Kw] k-major pack.
// ============================================================================
template<int OUTPACK, int BIAS, int RELU>
__global__ void __launch_bounds__(256, 2)
gemm_h(const uint32_t* __restrict__ A, const uint32_t* __restrict__ B,
       const float* __restrict__ bias,
       float* __restrict__ C, uint32_t* __restrict__ Cp,
       int M, int N, int Kw,
       size_t sAw, size_t sBw, size_t sCo)
{
    A += (size_t)blockIdx.z * sAw;
    B += (size_t)blockIdx.z * sBw;
    if (OUTPACK) Cp += (size_t)blockIdx.z * sCo;
    else         C  += (size_t)blockIdx.z * sCo;

    extern __shared__ uint32_t smh[];
    const uint32_t smbase = (uint32_t)__cvta_generic_to_shared(smh);

    const int tid  = threadIdx.x;
    const int lane = tid & 31;
    const int wid  = tid >> 5;
    const int g    = lane >> 2;
    const int tig  = lane & 3;
    const int wm   = wid & 1;
    const int wn   = wid >> 1;
    const int row0 = blockIdx.y * 128;
    const int col0 = blockIdx.x * 128;
    const int nwB  = wn * 32;

    const int aHi  = lane >> 4;
    const int la15 = lane & 15;
    const int bHi  = (lane >> 3) & 1;
    const int rbl  = (lane & 7) + ((lane >> 4) << 3);

    float acc[4][4][4];
#pragma unroll
    for (int mi = 0; mi < 4; mi++)
#pragma unroll
        for (int ni = 0; ni < 4; ni++)
#pragma unroll
            for (int j = 0; j < 4; j++) acc[mi][ni][j] = 0.f;

    auto issue = [&](int ktw, int s) {
        const uint32_t sa = smbase + s * (8192 * 4);
        const uint32_t sb = sa + 4096 * 4;
#pragma unroll
        for (int i = 0; i < 4; i++) {
            int flat = i * 256 + tid;
            int r = flat >> 3, c = flat & 7;
            const uint32_t* src = A + (size_t)(row0 + r) * Kw + ktw + c * 4;
            uint32_t dst = sa + (r * 32 + ((c ^ (r & 7)) << 2)) * 4;
            CP16(dst, src);
        }
#pragma unroll
        for (int i = 0; i < 4; i++) {
            int flat = i * 256 + tid;
            int r = flat >> 3, c = flat & 7;
            const uint32_t* src = B + (size_t)(col0 + r) * Kw + ktw + c * 4;
            uint32_t dst = sb + (r * 32 + ((c ^ (r & 7)) << 2)) * 4;
            CP16(dst, src);
        }
        CP_COMMIT();
    };

    auto compute = [&](int s) {
        const uint32_t sA = smbase + s * (8192 * 4);
        const uint32_t sB = sA + 4096 * 4;
#pragma unroll
        for (int ks = 0; ks < 4; ks++) {
            uint32_t a[4][4];
#pragma unroll
            for (int mi = 0; mi < 4; mi++) {
                const int ra = wm * 64 + mi * 16 + la15;
                LDSM4(a[mi][0], a[mi][1], a[mi][2], a[mi][3],
                      sA + ra * 128 + (((2 * ks + aHi) ^ (ra & 7)) << 4));
            }
#pragma unroll
            for (int p = 0; p < 2; p++) {
                const int rb = nwB + p * 16 + rbl;
                uint32_t b0, b1, b2, b3;
                LDSM4(b0, b1, b2, b3,
                      sB + rb * 128 + (((2 * ks + bHi) ^ (rb & 7)) << 4));
#pragma unroll
                for (int mi = 0; mi < 4; mi++) {
                    MMA_F16(acc[mi][2*p],   a[mi][0], a[mi][1], a[mi][2], a[mi][3], b0, b1);
                    MMA_F16(acc[mi][2*p+1], a[mi][0], a[mi][1], a[mi][2], a[mi][3], b2, b3);
                }
            }
        }
    };

    const int ktiles = Kw / 32;
    issue(0, 0);
    if (ktiles > 1) issue(32, 1);
    for (int t = 0; t < ktiles; t++) {
        if (t + 1 < ktiles) CP_WAIT1(); else CP_WAIT0();
        __syncthreads();
        compute(t % 3);
        if (t + 2 < ktiles) issue((t + 2) * 32, (t + 2) % 3);
    }

#pragma unroll
    for (int mi = 0; mi < 4; mi++) {
        const int r0 = row0 + wm * 64 + mi * 16 + g;
#pragma unroll
        for (int ni = 0; ni < 4; ni++) {
            const int c = col0 + nwB + ni * 8 + tig * 2;
            float f0 = acc[mi][ni][0], f1 = acc[mi][ni][1];
            float f2 = acc[mi][ni][2], f3 = acc[mi][ni][3];
            if (BIAS) {
                const float2 bb = *(const float2*)&bias[c];
                f0 += bb.x; f1 += bb.y; f2 += bb.x; f3 += bb.y;
            }
            if (RELU) {
                f0 = fmaxf(f0, 0.f); f1 = fmaxf(f1, 0.f);
                f2 = fmaxf(f2, 0.f); f3 = fmaxf(f3, 0.f);
            }
            if (OUTPACK) {
                const int Nw = N >> 1, wc = c >> 1;
                Cp[(size_t)r0 * Nw + wc]       = hpack(f0, f1);
                Cp[(size_t)(r0 + 8) * Nw + wc] = hpack(f2, f3);
            } else {
                *(float2*)&C[(size_t)r0 * N + c]       = make_float2(f0, f1);
                *(float2*)&C[(size_t)(r0 + 8) * N + c] = make_float2(f2, f3);
            }
        }
    }
}

// ============================================================================
// gemm_p: bf16 hi/lo 3-term GEMM, LDSM loads, 3-stage pipeline (R13 proven).
// ============================================================================
template<int OUTPACK, int BIAS>
__global__ void __launch_bounds__(256, 1)
gemm_p(const uint32_t* __restrict__ Ah, const uint32_t* __restrict__ Al,
       const uint32_t* __restrict__ Bh, const uint32_t* __restrict__ Bl,
       const float* __restrict__ bias,
       float* __restrict__ C, uint32_t* __restrict__ Ch, uint32_t* __restrict__ Cl,
       int M, int N, int Kw,
       size_t sAw, size_t sBw, size_t sCe)
{
    Ah += (size_t)blockIdx.z * sAw;  Al += (size_t)blockIdx.z * sAw;
    Bh += (size_t)blockIdx.z * sBw;  Bl += (size_t)blockIdx.z * sBw;
    if (!OUTPACK) C += (size_t)blockIdx.z * sCe;

    extern __shared__ uint32_t smp[];
    const uint32_t smbase = (uint32_t)__cvta_generic_to_shared(smp);

    const int tid  = threadIdx.x;
    const int lane = tid & 31;
    const int wid  = tid >> 5;
    const int g    = lane >> 2;
    const int tig  = lane & 3;
    const int wm   = wid & 1;
    const int wn   = wid >> 1;
    const int row0 = blockIdx.y * 128;
    const int col0 = blockIdx.x * 128;
    const int nwB  = wn * 32;

    const int aHi  = lane >> 4;
    const int la15 = lane & 15;
    const int bHi  = (lane >> 3) & 1;
    const int rbl  = (lane & 7) + ((lane >> 4) << 3);

    float acc[4][4][4];
#pragma unroll
    for (int mi = 0; mi < 4; mi++)
#pragma unroll
        for (int ni = 0; ni < 4; ni++)
#pragma unroll
            for (int j = 0; j < 4; j++) acc[mi][ni][j] = 0.f;

    auto issue = [&](int ktw, int s) {
        const uint32_t base = smbase + s * (8192 * 4);
        const uint32_t* gp[4] = { Ah, Al, Bh, Bl };
#pragma unroll
        for (int i = 0; i < 8; i++) {
            int flat = i * 256 + tid;
            int a    = flat >> 9;
            int rem  = flat & 511;
            int r    = rem >> 2;
            int c    = rem & 3;
            const int ro = (a < 2) ? row0 : col0;
            const uint32_t* src = gp[a] + (size_t)(ro + r) * Kw + ktw + c * 4;
            const int L = (a & 1) ? (c ^ 4) : c;
            const uint32_t side = (a < 2) ? 0u : 4096u * 4u;
            uint32_t dst = base + side + (r * 32 + ((L ^ (r & 7)) << 2)) * 4;
            CP16(dst, src);
        }
        CP_COMMIT();
    };

    auto compute = [&](int s) {
        const uint32_t sA = smbase + s * (8192 * 4);
        const uint32_t sB = sA + 4096 * 4;
#pragma unroll
        for (int ks = 0; ks < 2; ks++) {
            uint32_t ah[4][4], al[4][4];
#pragma unroll
            for (int mi = 0; mi < 4; mi++) {
                const int ra = wm * 64 + mi * 16 + la15;
                const uint32_t rbase = sA + ra * 128;
                const int ch = 2 * ks + aHi;
                LDSM4(ah[mi][0], ah[mi][1], ah[mi][2], ah[mi][3],
                      rbase + ((ch ^ (ra & 7)) << 4));
                LDSM4(al[mi][0], al[mi][1], al[mi][2], al[mi][3],
                      rbase + (((ch ^ 4) ^ (ra & 7)) << 4));
            }
#pragma unroll
            for (int p = 0; p < 2; p++) {
                const int rb = nwB + p * 16 + rbl;
                const uint32_t rbase = sB + rb * 128;
                const int ch = 2 * ks + bHi;
                uint32_t bh0, bh1, bh2, bh3, bl0, bl1, bl2, bl3;
                LDSM4(bh0, bh1, bh2, bh3, rbase + ((ch ^ (rb & 7)) << 4));
                LDSM4(bl0, bl1, bl2, bl3, rbase + (((ch ^ 4) ^ (rb & 7)) << 4));
#pragma unroll
                for (int mi = 0; mi < 4; mi++) {
                    MMA_BF16(acc[mi][2*p],   ah[mi][0], ah[mi][1], ah[mi][2], ah[mi][3], bh0, bh1);
                    MMA_BF16(acc[mi][2*p+1], ah[mi][0], ah[mi][1], ah[mi][2], ah[mi][3], bh2, bh3);
                }
#pragma unroll
                for (int mi = 0; mi < 4; mi++) {
                    MMA_BF16(acc[mi][2*p],   al[mi][0], al[mi][1], al[mi][2], al[mi][3], bh0, bh1);
                    MMA_BF16(acc[mi][2*p+1], al[mi][0], al[mi][1], al[mi][2], al[mi][3], bh2, bh3);
                }
#pragma unroll
                for (int mi = 0; mi < 4; mi++) {
                    MMA_BF16(acc[mi][2*p],   ah[mi][0], ah[mi][1], ah[mi][2], ah[mi][3], bl0, bl1);
                    MMA_BF16(acc[mi][2*p+1], ah[mi][0], ah[mi][1], ah[mi][2], ah[mi][3], bl2, bl3);
                }
            }
        }
    };

    const int ktiles = Kw / 16;
    issue(0, 0);
    if (ktiles > 1) issue(16, 1);
    for (int t = 0; t < ktiles; t++) {
        if (t + 1 < ktiles) CP_WAIT1(); else CP_WAIT0();
        __syncthreads();
        compute(t % 3);
        if (t + 2 < ktiles) issue((t + 2) * 16, (t + 2) % 3);
    }

#pragma unroll
    for (int mi = 0; mi < 4; mi++) {
        const int r0 = row0 + wm * 64 + mi * 16 + g;
#pragma unroll
        for (int ni = 0; ni < 4; ni++) {
            const int c = col0 + nwB + ni * 8 + tig * 2;
            float f0 = acc[mi][ni][0], f1 = acc[mi][ni][1];
            float f2 = acc[mi][ni][2], f3 = acc[mi][ni][3];
            if (BIAS) {
                const float2 bb = *(const float2*)&bias[c];
                f0 += bb.x; f1 += bb.y; f2 += bb.x; f3 += bb.y;
            }
            if (OUTPACK) {
                const int Nw = N >> 1, wc = c >> 1;
                uint32_t h0 = bfpack(f0, f1), h1 = bfpack(f2, f3);
                Ch[(size_t)r0 * Nw + wc]       = h0;
                Cl[(size_t)r0 * Nw + wc]       = bfres(f0, f1, h0);
                Ch[(size_t)(r0 + 8) * Nw + wc] = h1;
                Cl[(size_t)(r0 + 8) * Nw + wc] = bfres(f2, f3, h1);
            } else {
                *(float2*)&C[(size_t)r0 * N + c]       = make_float2(f0, f1);
                *(float2*)&C[(size_t)(r0 + 8) * N + c] = make_float2(f2, f3);
            }
        }
    }
}

// ---------------- pre-pass kernels ------------------------------------------
__global__ void pack_src2(const float* __restrict__ src,
                          uint32_t* __restrict__ Sh, uint32_t* __restrict__ Sl,
                          uint32_t* __restrict__ SrcH)
{
    const size_t row = blockIdx.x;
    const int t = threadIdx.x;
#pragma unroll
    for (int j = 0; j < 2; j++) {
        const int p = t + j * 256;
        const float2 v = *(const float2*)(src + row * EMBED + 2 * p);
        uint32_t h = bfpack(v.x, v.y);
        Sh[row * (EMBED/2) + p] = h;
        Sl[row * (EMBED/2) + p] = bfres(v.x, v.y, h);
        SrcH[row * (EMBED/2) + p] = hpack(v.x, v.y);
    }
}

// pack rows of W [R x 1024] into bf16 hi/lo k-major row pack
__global__ void pack_wrows(const float* __restrict__ W,
                           uint32_t* __restrict__ Rh, uint32_t* __restrict__ Rl)
{
    const size_t row = blockIdx.x;
    const int t = threadIdx.x;
#pragma unroll
    for (int j = 0; j < 2; j++) {
        const int p = t + j * 256;
        const float2 v = *(const float2*)(W + row * EMBED + 2 * p);
        uint32_t h = bfpack(v.x, v.y);
        Rh[row * (EMBED/2) + p] = h;
        Rl[row * (EMBED/2) + p] = bfres(v.x, v.y, h);
    }
}

__global__ void tpack_h(const float* __restrict__ A, uint32_t* __restrict__ At,
                        int K, int N, size_t sA, size_t sAt)
{
    A  += (size_t)blockIdx.z * sA;
    At += (size_t)blockIdx.z * sAt;
    __shared__ float tile[64][65];
    const int k0 = blockIdx.y * 64, n0 = blockIdx.x * 64;
    const int t = threadIdx.x;
#pragma unroll
    for (int i = 0; i < 4; i++) {
        int flat = i * 256 + t;
        int r = flat >> 4, c = (flat & 15) * 4;
        float4 v = *(const float4*)(A + (size_t)(k0 + r) * N + n0 + c);
        tile[r][c]     = v.x;
        tile[r][c + 1] = v.y;
        tile[r][c + 2] = v.z;
        tile[r][c + 3] = v.w;
    }
    __syncthreads();
#pragma unroll
    for (int i = 0; i < 8; i++) {
        int flat = i * 256 + t;
        int n = flat >> 5, w = flat & 31;
        At[(size_t)(n0 + n) * (K >> 1) + (k0 >> 1) + w] =
            hpack(tile[2 * w][n], tile[2 * w + 1][n]);
    }
}

// a[e] = Wq[e,:]·bk ; b[e] = Wk[e,:]·bq
__global__ void wvec_kernel(const float* __restrict__ Wq, const float* __restrict__ Wk,
                            const float* __restrict__ bk, const float* __restrict__ bq,
                            float* __restrict__ A, float* __restrict__ Bv)
{
    const size_t e = blockIdx.x;
    const int tid = threadIdx.x, lane = tid & 31, warp = tid >> 5;
    float4 wq = ((const float4*)(Wq + e * EMBED))[tid];
    float4 k4 = ((const float4*)bk)[tid];
    float4 wk = ((const float4*)(Wk + e * EMBED))[tid];
    float4 q4 = ((const float4*)bq)[tid];
    float s1 = wq.x*k4.x + wq.y*k4.y + wq.z*k4.z + wq.w*k4.w;
    float s2 = wk.x*q4.x + wk.y*q4.y + wk.z*q4.z + wk.w*q4.w;
    __shared__ float sh1[8], sh2[8];
#pragma unroll
    for (int o = 16; o > 0; o >>= 1) {
        s1 += __shfl_xor_sync(0xffffffffu, s1, o);
        s2 += __shfl_xor_sync(0xffffffffu, s2, o);
    }
    if (lane == 0) { sh1[warp] = s1; sh2[warp] = s2; }
    __syncthreads();
    if (tid == 0) {
        float t1 = 0.f, t2 = 0.f;
#pragma unroll
        for (int i = 0; i < 8; i++) { t1 += sh1[i]; t2 += sh2[i]; }
        A[e] = t1; Bv[e] = t2;
    }
}

// u[s] = src_s·a + bq·bk ; v[s] = src_s·b
__global__ void uv_kernel(const float* __restrict__ src,
                          const float* __restrict__ A, const float* __restrict__ Bv,
                          const float* __restrict__ bq, const float* __restrict__ bk,
                          float* __restrict__ U, float* __restrict__ V)
{
    const size_t s = blockIdx.x;
    const int tid = threadIdx.x, lane = tid & 31, warp = tid >> 5;
    float4 x  = ((const float4*)(src + s * EMBED))[tid];
    float4 a4 = ((const float4*)A)[tid];
    float4 b4 = ((const float4*)Bv)[tid];
    float4 q4 = ((const float4*)bq)[tid];
    float4 k4 = ((const float4*)bk)[tid];
    float s1 = x.x*a4.x + x.y*a4.y + x.z*a4.z + x.w*a4.w;
    float s2 = x.x*b4.x + x.y*b4.y + x.z*b4.z + x.w*b4.w;
    float s3 = q4.x*k4.x + q4.y*k4.y + q4.z*k4.z + q4.w*k4.w;
    __shared__ float sh1[8], sh2[8], sh3[8];
#pragma unroll
    for (int o = 16; o > 0; o >>= 1) {
        s1 += __shfl_xor_sync(0xffffffffu, s1, o);
        s2 += __shfl_xor_sync(0xffffffffu, s2, o);
        s3 += __shfl_xor_sync(0xffffffffu, s3, o);
    }
    if (lane == 0) { sh1[warp] = s1; sh2[warp] = s2; sh3[warp] = s3; }
    __syncthreads();
    if (tid == 0) {
        float t1 = 0.f, t2 = 0.f, t3 = 0.f;
#pragma unroll
        for (int i = 0; i < 8; i++) { t1 += sh1[i]; t2 += sh2[i]; t3 += sh3[i]; }
        U[s] = t1 + t3; V[s] = t2;
    }
}

// ---------------- softmax: scores + rank-1 terms -> packed fp16 attn --------
__global__ void softmax_kernel(const float* __restrict__ S,
                               const float* __restrict__ U, const float* __restrict__ V,
                               uint32_t* __restrict__ AtH)
{
    const size_t row = blockIdx.x;
    const float* p = S + row * SEQ;
    const float* vb = V + (row & ~(size_t)(SEQ - 1));   // batch base
    uint32_t* q = AtH + row * (SEQ/2);
    const int tid  = threadIdx.x;
    const int lane = tid & 31;
    const int warp = tid >> 5;
    const float us = U[row];

    float4 v0 = ((const float4*)p)[tid];
    float4 v1 = ((const float4*)p)[tid + 256];
    const float4 w0 = ((const float4*)vb)[tid];
    const float4 w1 = ((const float4*)vb)[tid + 256];
    v0.x += us + w0.x; v0.y += us + w0.y; v0.z += us + w0.z; v0.w += us + w0.w;
    v1.x += us + w1.x; v1.y += us + w1.y; v1.z += us + w1.z; v1.w += us + w1.w;

    __shared__ float sh[8];

    float m = fmaxf(fmaxf(fmaxf(v0.x, v0.y), fmaxf(v0.z, v0.w)),
                    fmaxf(fmaxf(v1.x, v1.y), fmaxf(v1.z, v1.w)));
#pragma unroll
    for (int o = 16; o > 0; o >>= 1) m = fmaxf(m, __shfl_xor_sync(0xffffffffu, m, o));
    if (lane == 0) sh[warp] = m;
    __syncthreads();
    if (tid < 32) {
        float t = (tid < 8) ? sh[tid] : -3.402823e38f;
#pragma unroll
        for (int o = 4; o > 0; o >>= 1) t = fmaxf(t, __shfl_xor_sync(0xffffffffu, t, o));
        if (tid == 0) sh[0] = t;
    }
    __syncthreads();
    m = sh[0];
    __syncthreads();

    v0.x = __expf(v0.x - m); v0.y = __expf(v0.y - m);
    v0.z = __expf(v0.z - m); v0.w = __expf(v0.w - m);
    v1.x = __expf(v1.x - m); v1.y = __expf(v1.y - m);
    v1.z = __expf(v1.z - m); v1.w = __expf(v1.w - m);

    float s = v0.x + v0.y + v0.z + v0.w + v1.x + v1.y + v1.z + v1.w;
#pragma unroll
    for (int o = 16; o > 0; o >>= 1) s += __shfl_xor_sync(0xffffffffu, s, o);
    if (lane == 0) sh[warp] = s;
    __syncthreads();
    if (tid < 32) {
        float t = (tid < 8) ? sh[tid] : 0.f;
#pragma unroll
        for (int o = 4; o > 0; o >>= 1) t += __shfl_xor_sync(0xffffffffu, t, o);
        if (tid == 0) sh[0] = t;
    }
    __syncthreads();
    const float r = 1.f / sh[0];

    q[2*tid]           = hpack(v0.x * r, v0.y * r);
    q[2*tid + 1]       = hpack(v0.z * r, v0.w * r);
    q[512 + 2*tid]     = hpack(v1.x * r, v1.y * r);
    q[512 + 2*tid + 1] = hpack(v1.z * r, v1.w * r);
}

// ---------------- residual + layernorm --------------------------------------
template<int WR>
__global__ void add_ln_kernel(const float* __restrict__ X, const float* __restrict__ Y,
                              const float* __restrict__ g, const float* __restrict__ b,
                              float* __restrict__ O, uint32_t* __restrict__ OH)
{
    const size_t row = blockIdx.x;
    const int tid  = threadIdx.x;
    const int lane = tid & 31;
    const int warp = tid >> 5;

    const float4 x = ((const float4*)(X + row * EMBED))[tid];
    const float4 y = ((const float4*)(Y + row * EMBED))[tid];
    float4 v;
    v.x = x.x + y.x; v.y = x.y + y.y; v.z = x.z + y.z; v.w = x.w + y.w;

    float s1 = v.x + v.y + v.z + v.w;
    float s2 = v.x * v.x + v.y * v.y + v.z * v.z + v.w * v.w;

    __shared__ float sh1[8], sh2[8];
#pragma unroll
    for (int o = 16; o > 0; o >>= 1) {
        s1 += __shfl_xor_sync(0xffffffffu, s1, o);
        s2 += __shfl_xor_sync(0xffffffffu, s2, o);
    }
    if (lane == 0) { sh1[warp] = s1; sh2[warp] = s2; }
    __syncthreads();
    if (tid < 32) {
        float t1 = (tid < 8) ? sh1[tid] : 0.f;
        float t2 = (tid < 8) ? sh2[tid] : 0.f;
#pragma unroll
        for (int o = 4; o > 0; o >>= 1) {
            t1 += __shfl_xor_sync(0xffffffffu, t1, o);
            t2 += __shfl_xor_sync(0xffffffffu, t2, o);
        }
        if (tid == 0) { sh1[0] = t1; sh2[0] = t2; }
    }
    __syncthreads();

    const float inv = 1.f / (float)EMBED;
    const float mu  = sh1[0] * inv;
    const float var = sh2[0] * inv - mu * mu;
    const float r   = rsqrtf(var + 1e-5f);

    const float4 gg = ((const float4*)g)[tid];
    const float4 bb = ((const float4*)b)[tid];
    float4 o;
    o.x = (v.x - mu) * r * gg.x + bb.x;
    o.y = (v.y - mu) * r * gg.y + bb.y;
    o.z = (v.z - mu) * r * gg.z + bb.z;
    o.w = (v.w - mu) * r * gg.w + bb.w;
    ((float4*)(O + row * EMBED))[tid] = o;
    if (WR) {
        OH[row * (EMBED/2) + 2*tid]     = hpack(o.x, o.y);
        OH[row * (EMBED/2) + 2*tid + 1] = hpack(o.z, o.w);
    }
}

// ---------------- launch -----------------------------------------------------
extern "C" void kernel_launch(void* const* d_in, const int* in_sizes, int n_in,
                              void* d_out, int out_size)
{
    const float* src = (const float*)d_in[0];
    const float* Wq  = (const float*)d_in[1];
    const float* bq  = (const float*)d_in[2];
    const float* Wk  = (const float*)d_in[3];
    const float* bk  = (const float*)d_in[4];
    const float* Wv  = (const float*)d_in[5];
    const float* bv  = (const float*)d_in[6];
    const float* Wo  = (const float*)d_in[7];
    const float* bo  = (const float*)d_in[8];
    const float* W1  = (const float*)d_in[9];
    const float* b1  = (const float*)d_in[10];
    const float* W2  = (const float*)d_in[11];
    const float* b2  = (const float*)d_in[12];
    const float* g1  = (const float*)d_in[13];
    const float* be1 = (const float*)d_in[14];
    const float* g2  = (const float*)d_in[15];
    const float* be2 = (const float*)d_in[16];

    float *S, *T, *AO, *X, *Vp, *va, *vb, *U, *V;
    uint32_t *SrcH, *XH, *AoH, *FH, *AtH, *VtH, *WvtH, *WotH, *W1tH, *W2tH;
    uint32_t *Sh, *Sl, *Ph, *Pl, *Mh, *Ml, *Wqr, *Wqrl, *Wkr, *Wkrl;
    cudaGetSymbolAddress((void**)&S,    g_S);
    cudaGetSymbolAddress((void**)&T,    g_T);
    cudaGetSymbolAddress((void**)&AO,   g_AO);
    cudaGetSymbolAddress((void**)&X,    g_X);
    cudaGetSymbolAddress((void**)&Vp,   g_Vp);
    cudaGetSymbolAddress((void**)&va,   g_va);
    cudaGetSymbolAddress((void**)&vb,   g_vb);
    cudaGetSymbolAddress((void**)&U,    g_u);
    cudaGetSymbolAddress((void**)&V,    g_v);
    cudaGetSymbolAddress((void**)&SrcH, g_SrcH);
    cudaGetSymbolAddress((void**)&XH,   g_XH);
    cudaGetSymbolAddress((void**)&AoH,  g_AoH);
    cudaGetSymbolAddress((void**)&FH,   g_FH);
    cudaGetSymbolAddress((void**)&AtH,  g_AtH);
    cudaGetSymbolAddress((void**)&VtH,  g_VtH);
    cudaGetSymbolAddress((void**)&WvtH, g_WvtH);
    cudaGetSymbolAddress((void**)&WotH, g_WotH);
    cudaGetSymbolAddress((void**)&W1tH, g_W1tH);
    cudaGetSymbolAddress((void**)&W2tH, g_W2tH);
    cudaGetSymbolAddress((void**)&Sh,   g_Sh);
    cudaGetSymbolAddress((void**)&Sl,   g_Sl);
    cudaGetSymbolAddress((void**)&Ph,   g_Ph);
    cudaGetSymbolAddress((void**)&Pl,   g_Pl);
    cudaGetSymbolAddress((void**)&Mh,   g_Mh);
    cudaGetSymbolAddress((void**)&Ml,   g_Ml);
    cudaGetSymbolAddress((void**)&Wqr,  g_Wqr);
    cudaGetSymbolAddress((void**)&Wqrl, g_Wqrl);
    cudaGetSymbolAddress((void**)&Wkr,  g_Wkr);
    cudaGetSymbolAddress((void**)&Wkrl, g_Wkrl);

    const int SMEM_P = 98304;    // gemm_p: 3 stages x 32KB
    const int SMEM_H = 98304;    // gemm_h: 3 stages x 32KB
    cudaFuncSetAttribute(gemm_p<1,0>,   cudaFuncAttributeMaxDynamicSharedMemorySize, SMEM_P);
    cudaFuncSetAttribute(gemm_p<0,0>,   cudaFuncAttributeMaxDynamicSharedMemorySize, SMEM_P);
    cudaFuncSetAttribute(gemm_h<0,1,0>, cudaFuncAttributeMaxDynamicSharedMemorySize, SMEM_H);
    cudaFuncSetAttribute(gemm_h<1,0,0>, cudaFuncAttributeMaxDynamicSharedMemorySize, SMEM_H);
    cudaFuncSetAttribute(gemm_h<1,1,1>, cudaFuncAttributeMaxDynamicSharedMemorySize, SMEM_H);

    const int KW = EMBED / 2;                       // 512 words
    const size_t sQEw = (size_t)SEQ * KW;
    const size_t sSS  = (size_t)SEQ * SEQ;
    const size_t sSSw = sSS / 2;
    const size_t sVt  = (size_t)EMBED * (SEQ/2);

    // launch order arranged so launch #4 (ncu capture slot) = gemm_h V-proj
    pack_src2<<<NROWS, 256>>>(src, Sh, Sl, SrcH);                       // 1
    tpack_h <<<dim3(16,16), 256>>>(Wv, WvtH, EMBED, EMBED, 0, 0);       // 2
    pack_wrows<<<EMBED, 256>>>(Wq, Wqr, Wqrl);                          // 3
    gemm_h<0,1,0><<<dim3(EMBED/128, NROWS/128), 256, SMEM_H>>>(SrcH, WvtH, bv,
        Vp, nullptr, NROWS, EMBED, KW, 0, 0, 0);                        // 4 <- profiled
    pack_wrows<<<EMBED, 256>>>(Wk, Wkr, Wkrl);
    wvec_kernel<<<EMBED, 256>>>(Wq, Wk, bk, bq, va, vb);
    uv_kernel<<<NROWS, 256>>>(src, va, vb, bq, bk, U, V);
    tpack_h <<<dim3(16,16), 256>>>(Wo, WotH, EMBED, EMBED, 0, 0);
    tpack_h <<<dim3(64,16), 256>>>(W1, W1tH, EMBED, DFF,   0, 0);
    tpack_h <<<dim3(16,64), 256>>>(W2, W2tH, DFF,   EMBED, 0, 0);

    // Mt = Wk · Wq^T  (Mt[f][e] row-packed over e -> B-operand for P)
    gemm_p<1,0><<<dim3(EMBED/128, EMBED/128), 256, SMEM_P>>>(Wkr, Wkrl, Wqr, Wqrl,
        nullptr, nullptr, Mh, Ml, EMBED, EMBED, KW, 0, 0, 0);

    // P = src · M  (A=src rows, B=Mt rows; replaces Q-proj; no bias)
    gemm_p<1,0><<<dim3(EMBED/128, NROWS/128), 256, SMEM_P>>>(Sh, Sl, Mh, Ml,
        nullptr, nullptr, Ph, Pl, NROWS, EMBED, KW, 0, 0, 0);

    // V^T pack per batch
    tpack_h<<<dim3(16, 32, NBATCH), 256>>>(Vp, VtH, SEQ, EMBED,
        (size_t)SEQ * EMBED, sVt);

    // scores = P · src^T (bf16 3-term) -> f32
    gemm_p<0,0><<<dim3(SEQ/128, SEQ/128, NBATCH), 256, SMEM_P>>>(Ph, Pl, Sh, Sl, nullptr,
        S, nullptr, nullptr, SEQ, SEQ, KW, sQEw, sQEw, sSS);

    // softmax (+ rank-1 bias terms) -> packed fp16 attn
    softmax_kernel<<<NROWS, 256>>>(S, U, V, AtH);

    // ao = attn @ V (fp16) -> packed
    gemm_h<1,0,0><<<dim3(EMBED/128, SEQ/128, NBATCH), 256, SMEM_H>>>(AtH, VtH, nullptr,
        nullptr, AoH, SEQ, EMBED, SEQ/2, sSSw, sVt, sQEw);

    // out-proj (fp16) -> f32
    gemm_h<0,1,0><<<dim3(EMBED/128, NROWS/128), 256, SMEM_H>>>(AoH, WotH, bo,
        AO, nullptr, NROWS, EMBED, KW, 0, 0, 0);

    add_ln_kernel<1><<<NROWS, 256>>>(src, AO, g1, be1, X, XH);

    // ff1 = relu(x @ W1 + b1) (fp16) -> packed
    gemm_h<1,1,1><<<dim3(DFF/128, NROWS/128), 256, SMEM_H>>>(XH, W1tH, b1,
        nullptr, FH, NROWS, DFF, KW, 0, 0, 0);

    // ff2 (fp16) -> f32
    gemm_h<0,1,0><<<dim3(EMBED/128, NROWS/128), 256, SMEM_H>>>(FH, W2tH, b2,
        T, nullptr, NROWS, EMBED, DFF/2, 0, 0, 0);

    add_ln_kernel<0><<<NROWS, 256>>>(X, T, g2, be2, (float*)d_out, nullptr);
}